// round 3
// baseline (speedup 1.0000x reference)
#include <cuda_runtime.h>
#include <cstdint>

#define BB 4
#define CC 512
#define KK 64
#define NN 1024

typedef unsigned long long ull;

// ---- scratch (static __device__, no allocations) ----
__device__ __align__(16) float g_inv[KK * CC];    // [k][c]  1/(sigma+1e-7)
__device__ __align__(16) float g_inv2t[CC * KK];  // [c][k]  inv^2
__device__ __align__(16) float g_m2t[CC * KK];    // [c][k]  -2*anchor*inv^2
__device__ __align__(16) float g_ck[KK];          // sum_c anchor^2*inv^2
__device__ __align__(16) float g_wpart[(NN / 32) * BB * KK];  // per-n-tile wsum partials
__device__ __align__(16) float g_part[4 * BB * KK * CC];      // split-N partials of num
__device__ __align__(16) float g_rc[BB * KK];                 // per-row flat-norm contribution

// ---- f32x2 helpers (sm_100+ packed fp32 FMA) ----
__device__ __forceinline__ ull pack2(float x, float y) {
    ull r; asm("mov.b64 %0, {%1,%2};" : "=l"(r) : "f"(x), "f"(y)); return r;
}
__device__ __forceinline__ ull fma2(ull a, ull b, ull c) {
    ull d; asm("fma.rn.f32x2 %0, %1, %2, %3;" : "=l"(d) : "l"(a), "l"(b), "l"(c)); return d;
}
__device__ __forceinline__ float2 unpack2(ull v) {
    float2 f; asm("mov.b64 {%0,%1}, %2;" : "=f"(f.x), "=f"(f.y) : "l"(v)); return f;
}

// ---- cp.async helpers ----
__device__ __forceinline__ void cp_async16(void* smem_dst, const void* gsrc) {
    unsigned sa = (unsigned)__cvta_generic_to_shared(smem_dst);
    asm volatile("cp.async.cg.shared.global [%0], [%1], 16;\n" :: "r"(sa), "l"(gsrc));
}
__device__ __forceinline__ void cp_commit() { asm volatile("cp.async.commit_group;\n"); }
template <int N>
__device__ __forceinline__ void cp_wait() { asm volatile("cp.async.wait_group %0;\n" :: "n"(N)); }

// ------------------------------------------------------------------
// Kernel 1: precompute per-(k,c) quantities + per-k constant
// ------------------------------------------------------------------
__global__ __launch_bounds__(256) void k1_prep(const float* __restrict__ anchor,
                                               const float* __restrict__ sp) {
    const int k = blockIdx.x;
    const int tid = threadIdx.x;
    float cks = 0.f;
#pragma unroll
    for (int r = 0; r < CC / 256; r++) {
        const int c = tid + r * 256;
        const float s = 1.f / (1.f + expf(-sp[k * CC + c]));
        const float inv = 1.f / (s + 1e-7f);
        const float inv2 = inv * inv;
        const float a = anchor[k * CC + c];
        g_inv[k * CC + c] = inv;
        g_inv2t[c * KK + k] = inv2;
        g_m2t[c * KK + k] = -2.f * a * inv2;
        cks += a * a * inv2;
    }
    __shared__ float red[256];
    red[tid] = cks;
    __syncthreads();
    for (int s = 128; s > 0; s >>= 1) {
        if (tid < s) red[tid] += red[tid + s];
        __syncthreads();
    }
    if (tid == 0) g_ck[k] = red[0];
}

// ------------------------------------------------------------------
// Kernel 2: d2 GEMM (64k x 32n, inner C=512) + fused softmax over K
// 256 threads, grid (NN/32, BB). Thread tile: 1 k-pair (f32x2) x 4 n.
// cp.async double-buffered c-chunks of 16. Parallel softmax tail.
// ------------------------------------------------------------------
__global__ __launch_bounds__(256) void k2_d2_softmax(const float* __restrict__ x,
                                                     float* __restrict__ soft_out) {
    const int b = blockIdx.y;
    const int nb = blockIdx.x;
    const int n0 = nb * 32;
    const int tid = threadIdx.x;
    const int tk = tid >> 3;  // 0..31 -> k pair base = tk*2
    const int tn = tid & 7;   // 0..7  -> n base = tn*4

    __shared__ __align__(16) float Wis[2][16 * 64];
    __shared__ __align__(16) float M2s[2][16 * 64];
    __shared__ __align__(16) float Xs[2][16 * 32];
    __shared__ float S[64 * 33];
    __shared__ float pm[256], ps[256];

    const float* xb = x + (size_t)b * CC * NN;

    auto issue = [&](int chunk, int buf) {
        const int c0 = chunk * 16;
        cp_async16(&Wis[buf][tid * 4], g_inv2t + c0 * KK + tid * 4);
        cp_async16(&M2s[buf][tid * 4], g_m2t + c0 * KK + tid * 4);
        if (tid < 128) {
            const int cc = tid >> 3, nn4 = (tid & 7) * 4;
            cp_async16(&Xs[buf][cc * 32 + nn4], xb + (size_t)(c0 + cc) * NN + n0 + nn4);
        }
        cp_commit();
    };

    ull acc[4];
#pragma unroll
    for (int j = 0; j < 4; j++) acc[j] = 0ull;

    issue(0, 0);
    for (int ch = 0; ch < 32; ch++) {
        if (ch + 1 < 32) { issue(ch + 1, (ch + 1) & 1); cp_wait<1>(); }
        else             { cp_wait<0>(); }
        __syncthreads();
        const float* Wb = Wis[ch & 1];
        const float* Mb = M2s[ch & 1];
        const float* Xb = Xs[ch & 1];
#pragma unroll
        for (int cc = 0; cc < 16; cc++) {
            const ull wp = *reinterpret_cast<const ull*>(Wb + cc * 64 + tk * 2);
            const ull mp = *reinterpret_cast<const ull*>(Mb + cc * 64 + tk * 2);
            const float4 xv = *reinterpret_cast<const float4*>(Xb + cc * 32 + tn * 4);
            const ull xd0 = pack2(xv.x, xv.x);
            const ull xd1 = pack2(xv.y, xv.y);
            const ull xd2 = pack2(xv.z, xv.z);
            const ull xd3 = pack2(xv.w, xv.w);
            ull t;
            t = fma2(wp, xd0, mp); acc[0] = fma2(t, xd0, acc[0]);
            t = fma2(wp, xd1, mp); acc[1] = fma2(t, xd1, acc[1]);
            t = fma2(wp, xd2, mp); acc[2] = fma2(t, xd2, acc[2]);
            t = fma2(wp, xd3, mp); acc[3] = fma2(t, xd3, acc[3]);
        }
        __syncthreads();
    }

    // logits -> shared (pad 33)
    {
        const int k0 = tk * 2;
        const float ck0 = g_ck[k0];
        const float ck1 = g_ck[k0 + 1];
#pragma unroll
        for (int j = 0; j < 4; j++) {
            const float2 v = unpack2(acc[j]);
            const int n = tn * 4 + j;
            S[k0 * 33 + n] = -0.5f * (v.x + ck0);
            S[(k0 + 1) * 33 + n] = -0.5f * (v.y + ck1);
        }
    }
    __syncthreads();

    // parallel softmax over K: thread (sub = tid>>5 handles 8 k, lane n = tid&31)
    {
        const int n = tid & 31;
        const int sub = tid >> 5;
        const int kb = sub * 8;
        float v[8];
#pragma unroll
        for (int i = 0; i < 8; i++) v[i] = S[(kb + i) * 33 + n];
        float m8 = v[0];
#pragma unroll
        for (int i = 1; i < 8; i++) m8 = fmaxf(m8, v[i]);
        pm[sub * 32 + n] = m8;
        __syncthreads();
        float m = pm[n];
#pragma unroll
        for (int j = 1; j < 8; j++) m = fmaxf(m, pm[j * 32 + n]);
        float e[8];
        float es = 0.f;
#pragma unroll
        for (int i = 0; i < 8; i++) { e[i] = __expf(v[i] - m); es += e[i]; }
        ps[sub * 32 + n] = es;
        __syncthreads();
        float s = ps[n];
#pragma unroll
        for (int j = 1; j < 8; j++) s += ps[j * 32 + n];
        const float invs = 1.f / s;
        float* outp = soft_out + (size_t)b * KK * NN + n0;
        float* wp = g_wpart + (nb * BB + b) * KK;
#pragma unroll
        for (int i = 0; i < 8; i++) {
            const float p = e[i] * invs;
            outp[(size_t)(kb + i) * NN + n] = p;
            float r = p;
#pragma unroll
            for (int o = 16; o > 0; o >>= 1) r += __shfl_xor_sync(0xffffffffu, r, o);
            if (n == 0) wp[kb + i] = r;
        }
    }
}

// ------------------------------------------------------------------
// Kernel 3: num[b,k,c] = sum_n A[b,k,n]*x[b,c,n], split-N=4 partials
// grid (CC/64, BB, 4), 256 threads, 64x64 tile, LDS.128 both operands
// ------------------------------------------------------------------
__global__ __launch_bounds__(256) void k3_num(const float* __restrict__ soft,
                                              const float* __restrict__ x) {
    const int b = blockIdx.y;
    const int c0 = blockIdx.x * 64;
    const int ns = blockIdx.z;
    const int nbeg = ns * (NN / 4);

    __shared__ __align__(16) float As[16 * 68];
    __shared__ __align__(16) float Xs[16 * 68];

    const int tid = threadIdx.x;
    const int tc = tid & 15;
    const int tk = tid >> 4;

    ull acc2[4][2];
#pragma unroll
    for (int i = 0; i < 4; i++) { acc2[i][0] = 0ull; acc2[i][1] = 0ull; }

    const float* Ab = soft + (size_t)b * KK * NN;
    const float* xb = x + (size_t)b * CC * NN;

    for (int n0 = nbeg; n0 < nbeg + NN / 4; n0 += 16) {
#pragma unroll
        for (int r = 0; r < 4; r++) {
            const int idx = tid + r * 256;  // 0..1023
            const int row = idx >> 4;       // 0..63
            const int nn = idx & 15;
            As[nn * 68 + row] = Ab[(size_t)row * NN + n0 + nn];
            Xs[nn * 68 + row] = xb[(size_t)(c0 + row) * NN + n0 + nn];
        }
        __syncthreads();
#pragma unroll
        for (int nn = 0; nn < 16; nn++) {
            const float4 a4 = *reinterpret_cast<const float4*>(&As[nn * 68 + tk * 4]);
            const ull ad0 = pack2(a4.x, a4.x);
            const ull ad1 = pack2(a4.y, a4.y);
            const ull ad2 = pack2(a4.z, a4.z);
            const ull ad3 = pack2(a4.w, a4.w);
            const float4 x4 = *reinterpret_cast<const float4*>(&Xs[nn * 68 + tc * 4]);
            const ull xq0 = pack2(x4.x, x4.y);
            const ull xq1 = pack2(x4.z, x4.w);
            acc2[0][0] = fma2(ad0, xq0, acc2[0][0]);
            acc2[0][1] = fma2(ad0, xq1, acc2[0][1]);
            acc2[1][0] = fma2(ad1, xq0, acc2[1][0]);
            acc2[1][1] = fma2(ad1, xq1, acc2[1][1]);
            acc2[2][0] = fma2(ad2, xq0, acc2[2][0]);
            acc2[2][1] = fma2(ad2, xq1, acc2[2][1]);
            acc2[3][0] = fma2(ad3, xq0, acc2[3][0]);
            acc2[3][1] = fma2(ad3, xq1, acc2[3][1]);
        }
        __syncthreads();
    }

    float* P = g_part + ((size_t)ns * BB + b) * KK * CC;
#pragma unroll
    for (int i = 0; i < 4; i++) {
        const float2 v0 = unpack2(acc2[i][0]);
        const float2 v1 = unpack2(acc2[i][1]);
        float4 o4 = make_float4(v0.x, v0.y, v1.x, v1.y);
        *reinterpret_cast<float4*>(&P[(size_t)(tk * 4 + i) * CC + c0 + tc * 4]) = o4;
    }
}

// ------------------------------------------------------------------
// Kernel 4: epilogue per (b,k): combine partials, subtract, scale, row-normalize
// grid (KK, BB), 128 threads. All independent LDGs issued before reductions.
// ------------------------------------------------------------------
__global__ __launch_bounds__(128) void k4_nodes(const float* __restrict__ anchor,
                                                float* __restrict__ nodes_out) {
    const int k = blockIdx.x;
    const int b = blockIdx.y;
    const int tid = threadIdx.x;

    __shared__ float wsh;
    __shared__ float red[4];
    __shared__ float rfs;

    // issue ALL independent loads first (max MLP)
    float wv = 0.f;
    if (tid < 32) wv = g_wpart[(tid * BB + b) * KK + k];
    const int c = tid * 4;
    float4 p0 = *reinterpret_cast<const float4*>(&g_part[((size_t)0 * BB + b) * KK * CC + (size_t)k * CC + c]);
    float4 p1 = *reinterpret_cast<const float4*>(&g_part[((size_t)1 * BB + b) * KK * CC + (size_t)k * CC + c]);
    float4 p2 = *reinterpret_cast<const float4*>(&g_part[((size_t)2 * BB + b) * KK * CC + (size_t)k * CC + c]);
    float4 p3 = *reinterpret_cast<const float4*>(&g_part[((size_t)3 * BB + b) * KK * CC + (size_t)k * CC + c]);
    const float4 a = *reinterpret_cast<const float4*>(&anchor[k * CC + c]);
    const float4 iv = *reinterpret_cast<const float4*>(&g_inv[k * CC + c]);

    if (tid < 32) {
#pragma unroll
        for (int o = 16; o > 0; o >>= 1) wv += __shfl_xor_sync(0xffffffffu, wv, o);
        if (tid == 0) wsh = wv;
    }
    __syncthreads();
    const float w = wsh;
    const float invden = 1.f / (w + 1e-7f);

    float4 s;
    s.x = (p0.x + p1.x) + (p2.x + p3.x);
    s.y = (p0.y + p1.y) + (p2.y + p3.y);
    s.z = (p0.z + p1.z) + (p2.z + p3.z);
    s.w = (p0.w + p1.w) + (p2.w + p3.w);
    float4 v;
    v.x = (s.x - w * a.x) * iv.x * invden;
    v.y = (s.y - w * a.y) * iv.y * invden;
    v.z = (s.z - w * a.z) * iv.z * invden;
    v.w = (s.w - w * a.w) * iv.w * invden;

    float ss = v.x * v.x + v.y * v.y + v.z * v.z + v.w * v.w;
#pragma unroll
    for (int o = 16; o > 0; o >>= 1) ss += __shfl_xor_sync(0xffffffffu, ss, o);
    if ((tid & 31) == 0) red[tid >> 5] = ss;
    __syncthreads();
    if (tid == 0) {
        const float sumsq = red[0] + red[1] + red[2] + red[3];
        const float rn = sqrtf(sumsq);
        const float rf = 1.f / fmaxf(rn, 1e-12f);
        g_rc[b * KK + k] = sumsq * rf * rf;
        rfs = rf;
    }
    __syncthreads();
    const float rf = rfs;
    float4 o4;
    o4.x = v.x * rf; o4.y = v.y * rf; o4.z = v.z * rf; o4.w = v.w * rf;
    *reinterpret_cast<float4*>(&nodes_out[((size_t)b * KK + k) * CC + c]) = o4;
}

// ------------------------------------------------------------------
// Kernel 5: flat normalization, grid (KK, BB), 128 threads
// ------------------------------------------------------------------
__global__ __launch_bounds__(128) void k5_scale(float* __restrict__ nodes_out) {
    const int k = blockIdx.x;
    const int b = blockIdx.y;
    const int tid = threadIdx.x;
    __shared__ float red[2];
    __shared__ float fsh;
    if (tid < 64) {
        float v = g_rc[b * KK + tid];
#pragma unroll
        for (int o = 16; o > 0; o >>= 1) v += __shfl_xor_sync(0xffffffffu, v, o);
        if ((tid & 31) == 0) red[tid >> 5] = v;
    }
    __syncthreads();
    if (tid == 0) fsh = 1.f / fmaxf(sqrtf(red[0] + red[1]), 1e-12f);
    __syncthreads();
    const float f = fsh;
    const int c = tid * 4;
    float4* p = reinterpret_cast<float4*>(&nodes_out[((size_t)b * KK + k) * CC + c]);
    float4 v = *p;
    v.x *= f; v.y *= f; v.z *= f; v.w *= f;
    *p = v;
}

// ------------------------------------------------------------------
extern "C" void kernel_launch(void* const* d_in, const int* in_sizes, int n_in,
                              void* d_out, int out_size) {
    (void)in_sizes; (void)n_in; (void)out_size;
    const float* x = (const float*)d_in[0];       // (4,512,32,32)
    const float* anchor = (const float*)d_in[1];  // (64,512)
    const float* sp = (const float*)d_in[2];      // (64,512)
    float* out = (float*)d_out;
    float* nodes_out = out;                        // B*K*C (viewed (B,C,K))
    float* soft_out = out + (size_t)BB * KK * CC;  // B*K*N

    k1_prep<<<KK, 256>>>(anchor, sp);
    k2_d2_softmax<<<dim3(NN / 32, BB), 256>>>(x, soft_out);
    k3_num<<<dim3(CC / 64, BB, 4), 256>>>(soft_out, x);
    k4_nodes<<<dim3(KK, BB), 128>>>(anchor, nodes_out);
    k5_scale<<<dim3(KK, BB), 128>>>(nodes_out);
}

// round 5
// speedup vs baseline: 1.0930x; 1.0930x over previous
#include <cuda_runtime.h>
#include <cstdint>

#define BB 4
#define CC 512
#define KK 64
#define NN 1024
#define NT 16   // k2 n-tile

typedef unsigned long long ull;

// ---- scratch (static __device__, no allocations) ----
__device__ __align__(16) float g_inv[KK * CC];    // [k][c]  1/(sigma+1e-7)
__device__ __align__(16) float g_inv2t[CC * KK];  // [c][k]  inv^2
__device__ __align__(16) float g_m2t[CC * KK];    // [c][k]  -2*anchor*inv^2
__device__ __align__(16) float g_ck[KK];          // sum_c anchor^2*inv^2
__device__ __align__(16) float g_wpart[(NN / NT) * BB * KK];  // per-n-tile wsum partials
__device__ __align__(16) float g_part[4 * BB * KK * CC];      // split-N partials of num
__device__ __align__(16) float g_rc[BB * KK];                 // per-row flat-norm contribution

// ---- f32x2 helpers (sm_100+ packed fp32 FMA) ----
__device__ __forceinline__ ull pack2(float x, float y) {
    ull r; asm("mov.b64 %0, {%1,%2};" : "=l"(r) : "f"(x), "f"(y)); return r;
}
__device__ __forceinline__ ull fma2(ull a, ull b, ull c) {
    ull d; asm("fma.rn.f32x2 %0, %1, %2, %3;" : "=l"(d) : "l"(a), "l"(b), "l"(c)); return d;
}
__device__ __forceinline__ float2 unpack2(ull v) {
    float2 f; asm("mov.b64 {%0,%1}, %2;" : "=f"(f.x), "=f"(f.y) : "l"(v)); return f;
}

// ---- cp.async helpers ----
__device__ __forceinline__ void cp_async16(void* smem_dst, const void* gsrc) {
    unsigned sa = (unsigned)__cvta_generic_to_shared(smem_dst);
    asm volatile("cp.async.cg.shared.global [%0], [%1], 16;\n" :: "r"(sa), "l"(gsrc));
}
__device__ __forceinline__ void cp_commit() { asm volatile("cp.async.commit_group;\n"); }
template <int N>
__device__ __forceinline__ void cp_wait() { asm volatile("cp.async.wait_group %0;\n" :: "n"(N)); }

// ------------------------------------------------------------------
// Kernel 1: precompute per-(k,c) quantities + per-k constant
// ------------------------------------------------------------------
__global__ __launch_bounds__(256) void k1_prep(const float* __restrict__ anchor,
                                               const float* __restrict__ sp) {
    const int k = blockIdx.x;
    const int tid = threadIdx.x;
    float cks = 0.f;
#pragma unroll
    for (int r = 0; r < CC / 256; r++) {
        const int c = tid + r * 256;
        const float s = 1.f / (1.f + __expf(-sp[k * CC + c]));
        const float inv = __fdividef(1.f, s + 1e-7f);
        const float inv2 = inv * inv;
        const float a = anchor[k * CC + c];
        g_inv[k * CC + c] = inv;
        g_inv2t[c * KK + k] = inv2;
        g_m2t[c * KK + k] = -2.f * a * inv2;
        cks += a * a * inv2;
    }
    __shared__ float red[256];
    red[tid] = cks;
    __syncthreads();
    for (int s = 128; s > 0; s >>= 1) {
        if (tid < s) red[tid] += red[tid + s];
        __syncthreads();
    }
    if (tid == 0) g_ck[k] = red[0];
}

// ------------------------------------------------------------------
// Kernel 2: d2 GEMM (64k x 16n, inner C=512) + fused softmax over K
// 128 threads, grid (NN/16, BB) = 256 blocks (~2/SM).
// Thread tile: 4k (two f32x2 pairs from one LDS.128) x 2n.
// cp.async double-buffered c-chunks of 16.
// ------------------------------------------------------------------
__global__ __launch_bounds__(128) void k2_d2_softmax(const float* __restrict__ x,
                                                     float* __restrict__ soft_out) {
    const int b = blockIdx.y;
    const int nb = blockIdx.x;
    const int n0 = nb * NT;
    const int tid = threadIdx.x;
    const int tk = tid >> 3;  // 0..15 -> k base = tk*4
    const int tn = tid & 7;   // 0..7  -> n base = tn*2

    __shared__ __align__(16) float Wis[2][16 * 64];
    __shared__ __align__(16) float M2s[2][16 * 64];
    __shared__ __align__(16) float Xs[2][16 * NT];
    __shared__ float S[64 * 17];

    const float* xb = x + (size_t)b * CC * NN;

    auto issue = [&](int chunk, int buf) {
        const int c0 = chunk * 16;
#pragma unroll
        for (int r = 0; r < 2; r++) {
            const int idx = tid + r * 128;  // float4 index 0..255
            cp_async16(&Wis[buf][idx * 4], g_inv2t + c0 * KK + idx * 4);
            cp_async16(&M2s[buf][idx * 4], g_m2t + c0 * KK + idx * 4);
        }
        if (tid < 64) {
            const int cc = tid >> 2, nn4 = (tid & 3) * 4;
            cp_async16(&Xs[buf][cc * NT + nn4], xb + (size_t)(c0 + cc) * NN + n0 + nn4);
        }
        cp_commit();
    };

    ull acc[2][2];
#pragma unroll
    for (int i = 0; i < 2; i++)
#pragma unroll
        for (int j = 0; j < 2; j++) acc[i][j] = 0ull;

    issue(0, 0);
    for (int ch = 0; ch < 32; ch++) {
        if (ch + 1 < 32) { issue(ch + 1, (ch + 1) & 1); cp_wait<1>(); }
        else             { cp_wait<0>(); }
        __syncthreads();
        const float* Wb = Wis[ch & 1];
        const float* Mb = M2s[ch & 1];
        const float* Xb = Xs[ch & 1];
#pragma unroll
        for (int cc = 0; cc < 16; cc++) {
            const ulonglong2 wp = *reinterpret_cast<const ulonglong2*>(Wb + cc * 64 + tk * 4);
            const ulonglong2 mp = *reinterpret_cast<const ulonglong2*>(Mb + cc * 64 + tk * 4);
            const float2 xv = *reinterpret_cast<const float2*>(Xb + cc * NT + tn * 2);
            const ull xd0 = pack2(xv.x, xv.x);
            const ull xd1 = pack2(xv.y, xv.y);
            ull t;
            t = fma2(wp.x, xd0, mp.x); acc[0][0] = fma2(t, xd0, acc[0][0]);
            t = fma2(wp.x, xd1, mp.x); acc[0][1] = fma2(t, xd1, acc[0][1]);
            t = fma2(wp.y, xd0, mp.y); acc[1][0] = fma2(t, xd0, acc[1][0]);
            t = fma2(wp.y, xd1, mp.y); acc[1][1] = fma2(t, xd1, acc[1][1]);
        }
        __syncthreads();
    }

    // logits -> shared (pad 17)
    {
        const int k0 = tk * 4;
#pragma unroll
        for (int kp = 0; kp < 2; kp++)
#pragma unroll
            for (int j = 0; j < 2; j++) {
                const float2 v = unpack2(acc[kp][j]);
                const int kk = k0 + kp * 2;
                const int n = tn * 2 + j;
                S[kk * 17 + n] = -0.5f * (v.x + g_ck[kk]);
                S[(kk + 1) * 17 + n] = -0.5f * (v.y + g_ck[kk + 1]);
            }
    }
    __syncthreads();

    // softmax over K per column (threads 0..15)
    if (tid < NT) {
        const int n = tid;
        float m = -1e30f;
#pragma unroll
        for (int k = 0; k < KK; k++) m = fmaxf(m, S[k * 17 + n]);
        float s = 0.f;
#pragma unroll
        for (int k = 0; k < KK; k++) s += __expf(S[k * 17 + n] - m);
        const float invs = 1.f / s;
        float* outp = soft_out + (size_t)b * KK * NN + n0 + n;
#pragma unroll
        for (int k = 0; k < KK; k++) {
            const float p = __expf(S[k * 17 + n] - m) * invs;
            S[k * 17 + n] = p;
            outp[(size_t)k * NN] = p;
        }
    }
    __syncthreads();

    // deterministic per-block wsum partial (threads 0..63, one per k)
    if (tid < 64) {
        const int k = tid;
        float s = 0.f;
#pragma unroll
        for (int n = 0; n < NT; n++) s += S[k * 17 + n];
        g_wpart[(nb * BB + b) * KK + k] = s;
    }
}

// ------------------------------------------------------------------
// Kernel 3: num[b,k,c] = sum_n A[b,k,n]*x[b,c,n], split-N=4 partials
// grid (CC/64, BB, 4), 256 threads, 64x64 tile, LDS.128 both operands
// ------------------------------------------------------------------
__global__ __launch_bounds__(256) void k3_num(const float* __restrict__ soft,
                                              const float* __restrict__ x) {
    const int b = blockIdx.y;
    const int c0 = blockIdx.x * 64;
    const int ns = blockIdx.z;
    const int nbeg = ns * (NN / 4);

    __shared__ __align__(16) float As[16 * 68];
    __shared__ __align__(16) float Xs[16 * 68];

    const int tid = threadIdx.x;
    const int tc = tid & 15;
    const int tk = tid >> 4;

    ull acc2[4][2];
#pragma unroll
    for (int i = 0; i < 4; i++) { acc2[i][0] = 0ull; acc2[i][1] = 0ull; }

    const float* Ab = soft + (size_t)b * KK * NN;
    const float* xb = x + (size_t)b * CC * NN;

    for (int n0 = nbeg; n0 < nbeg + NN / 4; n0 += 16) {
#pragma unroll
        for (int r = 0; r < 4; r++) {
            const int idx = tid + r * 256;  // 0..1023
            const int row = idx >> 4;       // 0..63
            const int nn = idx & 15;
            As[nn * 68 + row] = Ab[(size_t)row * NN + n0 + nn];
            Xs[nn * 68 + row] = xb[(size_t)(c0 + row) * NN + n0 + nn];
        }
        __syncthreads();
#pragma unroll
        for (int nn = 0; nn < 16; nn++) {
            const float4 a4 = *reinterpret_cast<const float4*>(&As[nn * 68 + tk * 4]);
            const ull ad0 = pack2(a4.x, a4.x);
            const ull ad1 = pack2(a4.y, a4.y);
            const ull ad2 = pack2(a4.z, a4.z);
            const ull ad3 = pack2(a4.w, a4.w);
            const float4 x4 = *reinterpret_cast<const float4*>(&Xs[nn * 68 + tc * 4]);
            const ull xq0 = pack2(x4.x, x4.y);
            const ull xq1 = pack2(x4.z, x4.w);
            acc2[0][0] = fma2(ad0, xq0, acc2[0][0]);
            acc2[0][1] = fma2(ad0, xq1, acc2[0][1]);
            acc2[1][0] = fma2(ad1, xq0, acc2[1][0]);
            acc2[1][1] = fma2(ad1, xq1, acc2[1][1]);
            acc2[2][0] = fma2(ad2, xq0, acc2[2][0]);
            acc2[2][1] = fma2(ad2, xq1, acc2[2][1]);
            acc2[3][0] = fma2(ad3, xq0, acc2[3][0]);
            acc2[3][1] = fma2(ad3, xq1, acc2[3][1]);
        }
        __syncthreads();
    }

    float* P = g_part + ((size_t)ns * BB + b) * KK * CC;
#pragma unroll
    for (int i = 0; i < 4; i++) {
        const float2 v0 = unpack2(acc2[i][0]);
        const float2 v1 = unpack2(acc2[i][1]);
        float4 o4 = make_float4(v0.x, v0.y, v1.x, v1.y);
        *reinterpret_cast<float4*>(&P[(size_t)(tk * 4 + i) * CC + c0 + tc * 4]) = o4;
    }
}

// ------------------------------------------------------------------
// Kernel 4: epilogue per (b,k): combine partials, subtract, scale, row-normalize
// grid (KK, BB), 128 threads. All independent LDGs issued before reductions.
// ------------------------------------------------------------------
__global__ __launch_bounds__(128) void k4_nodes(const float* __restrict__ anchor,
                                                float* __restrict__ nodes_out) {
    const int k = blockIdx.x;
    const int b = blockIdx.y;
    const int tid = threadIdx.x;

    __shared__ float redw[2];
    __shared__ float red[4];
    __shared__ float rfs;

    // issue ALL independent loads first (max MLP)
    float wv = 0.f;
    if (tid < 64) wv = g_wpart[(tid * BB + b) * KK + k];
    const int c = tid * 4;
    float4 p0 = *reinterpret_cast<const float4*>(&g_part[((size_t)0 * BB + b) * KK * CC + (size_t)k * CC + c]);
    float4 p1 = *reinterpret_cast<const float4*>(&g_part[((size_t)1 * BB + b) * KK * CC + (size_t)k * CC + c]);
    float4 p2 = *reinterpret_cast<const float4*>(&g_part[((size_t)2 * BB + b) * KK * CC + (size_t)k * CC + c]);
    float4 p3 = *reinterpret_cast<const float4*>(&g_part[((size_t)3 * BB + b) * KK * CC + (size_t)k * CC + c]);
    const float4 a = *reinterpret_cast<const float4*>(&anchor[k * CC + c]);
    const float4 iv = *reinterpret_cast<const float4*>(&g_inv[k * CC + c]);

    if (tid < 64) {
#pragma unroll
        for (int o = 16; o > 0; o >>= 1) wv += __shfl_xor_sync(0xffffffffu, wv, o);
        if ((tid & 31) == 0) redw[tid >> 5] = wv;
    }
    __syncthreads();
    const float w = redw[0] + redw[1];
    const float invden = 1.f / (w + 1e-7f);

    float4 s;
    s.x = (p0.x + p1.x) + (p2.x + p3.x);
    s.y = (p0.y + p1.y) + (p2.y + p3.y);
    s.z = (p0.z + p1.z) + (p2.z + p3.z);
    s.w = (p0.w + p1.w) + (p2.w + p3.w);
    float4 v;
    v.x = (s.x - w * a.x) * iv.x * invden;
    v.y = (s.y - w * a.y) * iv.y * invden;
    v.z = (s.z - w * a.z) * iv.z * invden;
    v.w = (s.w - w * a.w) * iv.w * invden;

    float ss = v.x * v.x + v.y * v.y + v.z * v.z + v.w * v.w;
#pragma unroll
    for (int o = 16; o > 0; o >>= 1) ss += __shfl_xor_sync(0xffffffffu, ss, o);
    if ((tid & 31) == 0) red[tid >> 5] = ss;
    __syncthreads();
    if (tid == 0) {
        const float sumsq = red[0] + red[1] + red[2] + red[3];
        const float rn = sqrtf(sumsq);
        const float rf = 1.f / fmaxf(rn, 1e-12f);
        g_rc[b * KK + k] = sumsq * rf * rf;
        rfs = rf;
    }
    __syncthreads();
    const float rf = rfs;
    float4 o4;
    o4.x = v.x * rf; o4.y = v.y * rf; o4.z = v.z * rf; o4.w = v.w * rf;
    *reinterpret_cast<float4*>(&nodes_out[((size_t)b * KK + k) * CC + c]) = o4;
}

// ------------------------------------------------------------------
// Kernel 5: flat normalization, grid (KK, BB), 128 threads
// ------------------------------------------------------------------
__global__ __launch_bounds__(128) void k5_scale(float* __restrict__ nodes_out) {
    const int k = blockIdx.x;
    const int b = blockIdx.y;
    const int tid = threadIdx.x;
    __shared__ float red[2];
    __shared__ float fsh;
    if (tid < 64) {
        float v = g_rc[b * KK + tid];
#pragma unroll
        for (int o = 16; o > 0; o >>= 1) v += __shfl_xor_sync(0xffffffffu, v, o);
        if ((tid & 31) == 0) red[tid >> 5] = v;
    }
    __syncthreads();
    if (tid == 0) fsh = 1.f / fmaxf(sqrtf(red[0] + red[1]), 1e-12f);
    __syncthreads();
    const float f = fsh;
    const int c = tid * 4;
    float4* p = reinterpret_cast<float4*>(&nodes_out[((size_t)b * KK + k) * CC + c]);
    float4 v = *p;
    v.x *= f; v.y *= f; v.z *= f; v.w *= f;
    *p = v;
}

// ------------------------------------------------------------------
extern "C" void kernel_launch(void* const* d_in, const int* in_sizes, int n_in,
                              void* d_out, int out_size) {
    (void)in_sizes; (void)n_in; (void)out_size;
    const float* x = (const float*)d_in[0];       // (4,512,32,32)
    const float* anchor = (const float*)d_in[1];  // (64,512)
    const float* sp = (const float*)d_in[2];      // (64,512)
    float* out = (float*)d_out;
    float* nodes_out = out;                        // B*K*C (viewed (B,C,K))
    float* soft_out = out + (size_t)BB * KK * CC;  // B*K*N

    k1_prep<<<KK, 256>>>(anchor, sp);
    k2_d2_softmax<<<dim3(NN / NT, BB), 128>>>(x, soft_out);
    k3_num<<<dim3(CC / 64, BB, 4), 256>>>(soft_out, x);
    k4_nodes<<<dim3(KK, BB), 128>>>(anchor, nodes_out);
    k5_scale<<<dim3(KK, BB), 128>>>(nodes_out);
}